// round 9
// baseline (speedup 1.0000x reference)
#include <cuda_runtime.h>
#include <cuda_bf16.h>
#include <math.h>
#include <stdint.h>

// ---------------------------------------------------------------------------
// Round 8:
//   corr : A operand via ldmatrix.trans from k-major tile (p = oj*8+oi) ->
//          contiguous STS.64 blend stores; packed cvt.rn.bf16x2 splits.
//   mlp1 : 64x128 tile, 256 threads, dynamic smem (3 CTA/SM), halved X traffic.
//   mlp2 : unchanged 64x64 split GEMM.
// ---------------------------------------------------------------------------

#define NPTS 4096
#define CC   128
#define LDK  2432
#define MTOT (4 * NPTS)

__device__ __nv_bfloat16 g_Xh[MTOT * LDK];
__device__ __nv_bfloat16 g_Xl[MTOT * LDK];
__device__ __nv_bfloat16 g_Wh[384 * LDK];
__device__ __nv_bfloat16 g_Wl[384 * LDK];
__device__ __nv_bfloat16 g_Hh[MTOT * 384];
__device__ __nv_bfloat16 g_Hl[MTOT * 384];
__device__ __nv_bfloat16 g_W2h[256 * 384];
__device__ __nv_bfloat16 g_W2l[256 * 384];

// ---------------- helpers ----------------------------------------------------
__device__ __forceinline__ uint32_t smem_u32(const void* p) {
    uint32_t a;
    asm("{ .reg .u64 t; cvta.to.shared.u64 t, %1; cvt.u32.u64 %0, t; }"
        : "=r"(a) : "l"(p));
    return a;
}

#define LDSM4(r, addr)                                                        \
    asm volatile("ldmatrix.sync.aligned.m8n8.x4.shared.b16 {%0,%1,%2,%3}, [%4];" \
        : "=r"((r)[0]), "=r"((r)[1]), "=r"((r)[2]), "=r"((r)[3]) : "r"(addr))

#define LDSM4T(r, addr)                                                       \
    asm volatile("ldmatrix.sync.aligned.m8n8.x4.trans.shared.b16 {%0,%1,%2,%3}, [%4];" \
        : "=r"((r)[0]), "=r"((r)[1]), "=r"((r)[2]), "=r"((r)[3]) : "r"(addr))

#define MMA16816(d, a, b)                                                     \
    asm volatile("mma.sync.aligned.m16n8k16.row.col.f32.bf16.bf16.f32 "       \
        "{%0,%1,%2,%3}, {%4,%5,%6,%7}, {%8,%9}, {%0,%1,%2,%3};"               \
        : "+f"((d)[0]), "+f"((d)[1]), "+f"((d)[2]), "+f"((d)[3])              \
        : "r"((a)[0]), "r"((a)[1]), "r"((a)[2]), "r"((a)[3]),                 \
          "r"((b)[0]), "r"((b)[1]))

#define CP16(dst, src)                                                        \
    asm volatile("cp.async.cg.shared.global [%0], [%1], 16;" :: "r"(dst), "l"(src))
#define CP_COMMIT() asm volatile("cp.async.commit_group;" ::: "memory")

__device__ __forceinline__ void split_bf16(float x, __nv_bfloat16& h, __nv_bfloat16& l) {
    h = __float2bfloat16(x);
    l = __float2bfloat16(x - __bfloat162float(h));
}

// pack two floats (lo, hi) into bf16x2 with rn rounding
__device__ __forceinline__ uint32_t cvt2bf(float hi, float lo) {
    uint32_t d;
    asm("cvt.rn.bf16x2.f32 %0, %1, %2;" : "=r"(d) : "f"(hi), "f"(lo));
    return d;
}

// 4-float -> (h01,h23,l01,l23) packed split
__device__ __forceinline__ void split4(float o0, float o1, float o2, float o3,
                                       uint2& hh, uint2& ll) {
    uint32_t h01 = cvt2bf(o1, o0);
    uint32_t h23 = cvt2bf(o3, o2);
    float l0 = o0 - __uint_as_float(h01 << 16);
    float l1 = o1 - __uint_as_float(h01 & 0xFFFF0000u);
    float l2 = o2 - __uint_as_float(h23 << 16);
    float l3 = o3 - __uint_as_float(h23 & 0xFFFF0000u);
    hh = make_uint2(h01, h23);
    ll = make_uint2(cvt2bf(l1, l0), cvt2bf(l3, l2));
}

// ---------------- corr kernel ------------------------------------------------
#define TSR  40     // T tile row stride (bf16)
#define ASTR 72     // Acol (k-major) row stride (bf16)

struct CorrParams {
    const float* fmap[4];
    const float* tfeat[4];
    int   Hh[4];
    int   Ww[4];
    float ls[4];
};

template<int K, int I>
struct QB {
    static __device__ __forceinline__ void run(float* q, const float* rv,
                                               float w0, float w1) {
        float v0 = 0.f, v1 = 0.f;
        if constexpr (K + I >= 0 && K + I <= 11)         v0 = rv[K + I];
        if constexpr (K + I + 1 >= 0 && K + I + 1 <= 11) v1 = rv[K + I + 1];
        q[I] = w0 * v0 + w1 * v1;
        if constexpr (I < 6) QB<K, I + 1>::run(q, rv, w0, w1);
    }
};
template<int K>
__device__ __forceinline__ void qrow_blend(float* q, const float* rv,
                                           float w0, float w1) {
    QB<K, 0>::run(q, rv, w0, w1);
}

__global__ __launch_bounds__(128) void corr_main(
    CorrParams P, const float* __restrict__ coords)
{
    __shared__ float Qs[2048];                            // 32c x 8y x 8x
    __shared__ __align__(16) float Tf[2][1568];           // tfeat fp32 stage
    __shared__ __align__(16) __nv_bfloat16 tAh[32 * ASTR]; // A k-major [c][p]
    __shared__ __align__(16) __nv_bfloat16 tAl[32 * ASTR];
    __shared__ __align__(16) __nv_bfloat16 tTh[64 * TSR];  // T [q][c]
    __shared__ __align__(16) __nv_bfloat16 tTl[64 * TSR];

    const int n    = blockIdx.x;
    const int lvl  = blockIdx.y;
    const int t    = threadIdx.x;
    const int w    = t >> 5;
    const int lane = t & 31;

    const float* __restrict__ fmap  = P.fmap[lvl];
    const float* __restrict__ tfeat = P.tfeat[lvl];
    const int Hh = P.Hh[lvl], Ww = P.Ww[lvl];

    const float xl = __ldg(&coords[2 * n + 0]) * P.ls[lvl];
    const float yl = __ldg(&coords[2 * n + 1]) * P.ls[lvl];
    const float xf = floorf(xl), yf = floorf(yl);
    const float wx = xl - xf, wy = yl - yf;
    const int bx = (int)xf - 3, by = (int)yf - 3;
    const float w0x = 1.f - wx, w1x = wx;
    const float w0y = 1.f - wy, w1y = wy;

    int s  = min(max(bx, 0), Ww - 8);
    int al = min(max(s & ~3, 0), Ww - 12);
    const int shift = bx - al;

    const uint32_t aAh = smem_u32(tAh);
    const uint32_t aAl = smem_u32(tAl);
    const uint32_t aTh = smem_u32(tTh);
    const uint32_t aTl = smem_u32(tTl);
    const uint32_t aTf = smem_u32(Tf);

    const int wm = (w & 1) * 32;
    const int wn = (w >> 1) * 32;

    float acc[2][4][4];
#pragma unroll
    for (int i = 0; i < 2; i++)
#pragma unroll
        for (int j = 0; j < 4; j++)
#pragma unroll
            for (int r = 0; r < 4; r++) acc[i][j][r] = 0.f;

    auto issue_tfeat = [&](int qi, int buf) {
        const int c0 = qi * 32;
#pragma unroll
        for (int e = t; e < 392; e += 128) {
            const int q  = e >> 3;
            const int c4 = (e & 7) << 2;
            CP16(aTf + (uint32_t)(buf * 1568 + e * 4) * 4,
                 tfeat + (size_t)q * (NPTS * CC) + n * CC + c0 + c4);
        }
        CP_COMMIT();
    };
    issue_tfeat(0, 0);

    for (int qi = 0; qi < 4; qi++) {
        const int c0 = qi * 32;

        // ---- patch rows -> x-blended Q rows ----
#pragma unroll
        for (int it = 0; it < 2; it++) {
            const int r  = t + 128 * it;
            const int c  = r >> 3;
            const int yy = r & 7;
            const int gy = by + yy;
            float rv[12];
#pragma unroll
            for (int j = 0; j < 12; j++) rv[j] = 0.f;
            if (gy >= 0 && gy < Hh) {
                const float4* rp = reinterpret_cast<const float4*>(
                    fmap + ((size_t)(c0 + c) * Hh + gy) * Ww + al);
                float4 f0 = __ldg(rp), f1 = __ldg(rp + 1), f2 = __ldg(rp + 2);
                rv[0]=f0.x; rv[1]=f0.y; rv[2]=f0.z; rv[3]=f0.w;
                rv[4]=f1.x; rv[5]=f1.y; rv[6]=f1.z; rv[7]=f1.w;
                rv[8]=f2.x; rv[9]=f2.y; rv[10]=f2.z; rv[11]=f2.w;
            }
            float q[7];
            switch (shift) {
                case -3: qrow_blend<-3>(q, rv, w0x, w1x); break;
                case -2: qrow_blend<-2>(q, rv, w0x, w1x); break;
                case -1: qrow_blend<-1>(q, rv, w0x, w1x); break;
                case  0: qrow_blend< 0>(q, rv, w0x, w1x); break;
                case  1: qrow_blend< 1>(q, rv, w0x, w1x); break;
                case  2: qrow_blend< 2>(q, rv, w0x, w1x); break;
                case  3: qrow_blend< 3>(q, rv, w0x, w1x); break;
                case  4: qrow_blend< 4>(q, rv, w0x, w1x); break;
                case  5: qrow_blend< 5>(q, rv, w0x, w1x); break;
                case  6: qrow_blend< 6>(q, rv, w0x, w1x); break;
                case  7: qrow_blend< 7>(q, rv, w0x, w1x); break;
                default: qrow_blend< 8>(q, rv, w0x, w1x); break;
            }
            float4* Qp = reinterpret_cast<float4*>(&Qs[c * 64 + yy * 8]);
            Qp[0] = make_float4(q[0], q[1], q[2], q[3]);
            Qp[1] = make_float4(q[4], q[5], q[6], 0.f);
        }

        if (qi + 1 < 4) {
            issue_tfeat(qi + 1, (qi + 1) & 1);
            asm volatile("cp.async.wait_group 1;" ::: "memory");
        } else {
            asm volatile("cp.async.wait_group 0;" ::: "memory");
        }
        __syncthreads();

        // ---- tfeat quarter -> T tiles (packed split, STS.64) ----
        const float* Tc = Tf[qi & 1];
#pragma unroll
        for (int e = t; e < 392; e += 128) {
            const int q  = e >> 3;
            const int c4 = (e & 7) << 2;
            float4 v = *reinterpret_cast<const float4*>(&Tc[e * 4]);
            uint2 hh, ll;
            split4(v.x, v.y, v.z, v.w, hh, ll);
            *reinterpret_cast<uint2*>(&tTh[q * TSR + c4]) = hh;
            *reinterpret_cast<uint2*>(&tTl[q * TSR + c4]) = ll;
        }

        // ---- y-blend -> Acol[c][p], p = oj*8 + oi (contiguous STS.64) ----
#pragma unroll
        for (int e = t; e < 448; e += 128) {
            const int c  = e / 14;
            const int r  = e - c * 14;
            const int oj = r >> 1;
            const int h4 = (r & 1) * 4;
            float4 qa = *reinterpret_cast<const float4*>(&Qs[c * 64 + oj * 8 + h4]);
            float4 qb = *reinterpret_cast<const float4*>(&Qs[c * 64 + (oj + 1) * 8 + h4]);
            uint2 hh, ll;
            split4(w0y * qa.x + w1y * qb.x, w0y * qa.y + w1y * qb.y,
                   w0y * qa.z + w1y * qb.z, w0y * qa.w + w1y * qb.w, hh, ll);
            const int pos = c * ASTR + oj * 8 + h4;
            *reinterpret_cast<uint2*>(&tAh[pos]) = hh;
            *reinterpret_cast<uint2*>(&tAl[pos]) = ll;
        }
        __syncthreads();

        // ---- MMA: A via ldmatrix.trans (k-major), B via ldmatrix ----
#pragma unroll
        for (int ks = 0; ks < 2; ks++) {
            const int kc = ks * 16;
            uint32_t ah[2][4], alf[2][4], bh[4][2], bl[4][2];
            const int arow = kc + (lane & 7) + ((lane >> 4) << 3);
#pragma unroll
            for (int i = 0; i < 2; i++) {
                const int acol = wm + i * 16 + ((lane >> 3) & 1) * 8;
                const uint32_t off = (uint32_t)(arow * ASTR + acol) * 2;
                LDSM4T(ah[i], aAh + off);
                LDSM4T(alf[i], aAl + off);
            }
#pragma unroll
            for (int p = 0; p < 2; p++) {
                const uint32_t off =
                    (uint32_t)((wn + p * 16 + ((lane >> 4) & 1) * 8 + (lane & 7)) * TSR
                               + kc + ((lane >> 3) & 1) * 8) * 2;
                uint32_t rh[4], rl[4];
                LDSM4(rh, aTh + off);
                LDSM4(rl, aTl + off);
                bh[2 * p][0] = rh[0]; bh[2 * p][1] = rh[1];
                bh[2 * p + 1][0] = rh[2]; bh[2 * p + 1][1] = rh[3];
                bl[2 * p][0] = rl[0]; bl[2 * p][1] = rl[1];
                bl[2 * p + 1][0] = rl[2]; bl[2 * p + 1][1] = rl[3];
            }
#pragma unroll
            for (int i = 0; i < 2; i++)
#pragma unroll
                for (int j = 0; j < 4; j++) {
                    MMA16816(acc[i][j], ah[i], bh[j]);
                    MMA16816(acc[i][j], ah[i], bl[j]);
                    MMA16816(acc[i][j], alf[i], bh[j]);
                }
        }
        __syncthreads();
    }

    // ---- epilogue: m = oj*8+oi -> hw = oi*7+oj ----
    __nv_bfloat16* Xh = g_Xh + ((size_t)lvl * NPTS + n) * LDK;
    __nv_bfloat16* Xl = g_Xl + ((size_t)lvl * NPTS + n) * LDK;
#pragma unroll
    for (int i = 0; i < 2; i++)
#pragma unroll
        for (int rr = 0; rr < 2; rr++) {
            const int m  = wm + i * 16 + (lane >> 2) + rr * 8;
            const int oi = m & 7, oj = m >> 3;
            if (oi < 7 && oj < 7) {
                const int base = (oi * 7 + oj) * 49;
#pragma unroll
                for (int j = 0; j < 4; j++) {
                    const int q0 = wn + j * 8 + (lane & 3) * 2;
                    __nv_bfloat16 h, l;
                    if (q0 < 49) {
                        split_bf16(acc[i][j][rr * 2 + 0], h, l);
                        Xh[base + q0] = h; Xl[base + q0] = l;
                    }
                    if (q0 + 1 < 49) {
                        split_bf16(acc[i][j][rr * 2 + 1], h, l);
                        Xh[base + q0 + 1] = h; Xl[base + q0 + 1] = l;
                    }
                }
            }
        }
}

// ---------------- prep: split + transpose weights ---------------------------
__global__ __launch_bounds__(128) void split_w1(const float* __restrict__ w1)
{
    const int k = blockIdx.x;
    const float* row = w1 + (size_t)k * 384;
    for (int n = threadIdx.x; n < 384; n += 128) {
        __nv_bfloat16 h, l;
        split_bf16(row[n], h, l);
        g_Wh[(size_t)n * LDK + k] = h;
        g_Wl[(size_t)n * LDK + k] = l;
    }
}

__global__ __launch_bounds__(128) void split_w2(const float* __restrict__ w2)
{
    const int k = blockIdx.x;
    const float* row = w2 + (size_t)k * 256;
    for (int n = threadIdx.x; n < 256; n += 128) {
        __nv_bfloat16 h, l;
        split_bf16(row[n], h, l);
        g_W2h[(size_t)n * 384 + k] = h;
        g_W2l[(size_t)n * 384 + k] = l;
    }
}

// ---------------- MLP1: 64x128 tile, 256 threads, dynamic smem --------------
#define BK    32
#define M1A   2560              // 64*40   (bf16 per A mat)
#define M1B   5120              // 128*40  (bf16 per B mat)
#define M1STG (2 * M1A + 2 * M1B)   // 15360 bf16 per stage
#define NCH   (LDK / BK)        // 76

__global__ __launch_bounds__(256) void mlp1_mma(const float* __restrict__ b1)
{
    extern __shared__ __align__(16) __nv_bfloat16 sm1[];

    const int t    = threadIdx.x;
    const int w    = t >> 5;
    const int lane = t & 31;
    const int m0   = blockIdx.x * 64;
    const int n0   = blockIdx.y * 128;
    const uint32_t sb = smem_u32(sm1);

    float acc[2][4][4];
#pragma unroll
    for (int i = 0; i < 2; i++)
#pragma unroll
        for (int j = 0; j < 4; j++)
#pragma unroll
            for (int r = 0; r < 4; r++) acc[i][j][r] = 0.f;

    const __nv_bfloat16* gA[2] = { g_Xh + (size_t)m0 * LDK, g_Xl + (size_t)m0 * LDK };
    const __nv_bfloat16* gB[2] = { g_Wh + (size_t)n0 * LDK, g_Wl + (size_t)n0 * LDK };

    auto load_stage = [&](int ch, int st) {
#pragma unroll
        for (int it = 0; it < 6; it++) {
            const int u = t + 256 * it;
            const __nv_bfloat16* src;
            uint32_t dstoff;
            if (u < 512) {
                const int mat = u >> 8, row = (u >> 2) & 63, c16 = u & 3;
                src = gA[mat] + (size_t)row * LDK + ch * BK + c16 * 8;
                dstoff = st * M1STG + mat * M1A + row * TSR + c16 * 8;
            } else {
                const int v = u - 512;
                const int mat = v >> 9, row = (v >> 2) & 127, c16 = v & 3;
                src = gB[mat] + (size_t)row * LDK + ch * BK + c16 * 8;
                dstoff = st * M1STG + 2 * M1A + mat * M1B + row * TSR + c16 * 8;
            }
            CP16(sb + dstoff * 2, src);
        }
        CP_COMMIT();
    };

    load_stage(0, 0);

    const int wm = (w & 1) * 32;
    const int wn = (w >> 1) * 32;

    for (int ch = 0; ch < NCH; ch++) {
        if (ch + 1 < NCH) {
            load_stage(ch + 1, (ch + 1) & 1);
            asm volatile("cp.async.wait_group 1;" ::: "memory");
        } else {
            asm volatile("cp.async.wait_group 0;" ::: "memory");
        }
        __syncthreads();

        const uint32_t sa = sb + (uint32_t)((ch & 1) * M1STG) * 2;
        const uint32_t Ah = sa;
        const uint32_t Al = sa + M1A * 2;
        const uint32_t Bh = sa + 2 * M1A * 2;
        const uint32_t Bl = sa + (2 * M1A + M1B) * 2;

#pragma unroll
        for (int ks = 0; ks < 2; ks++) {
            const int kc = ks * 16;
            uint32_t ah[2][4], alf[2][4], bh[4][2], bl[4][2];
#pragma unroll
            for (int i = 0; i < 2; i++) {
                const uint32_t off =
                    (uint32_t)((wm + i * 16 + (lane & 15)) * TSR + kc + (lane >> 4) * 8) * 2;
                LDSM4(ah[i], Ah + off);
                LDSM4(alf[i], Al + off);
            }
#pragma unroll
            for (int p = 0; p < 2; p++) {
                const uint32_t off =
                    (uint32_t)((wn + p * 16 + ((lane >> 4) & 1) * 8 + (lane & 7)) * TSR
                               + kc + ((lane >> 3) & 1) * 8) * 2;
                uint32_t rh[4], rl[4];
                LDSM4(rh, Bh + off);
                LDSM4(rl, Bl + off);
                bh[2 * p][0] = rh[0]; bh[2 * p][1] = rh[1];
                bh[2 * p + 1][0] = rh[2]; bh[2 * p + 1][1] = rh[3];
                bl[2 * p][0] = rl[0]; bl[2 * p][1] = rl[1];
                bl[2 * p + 1][0] = rl[2]; bl[2 * p + 1][1] = rl[3];
            }
#pragma unroll
            for (int i = 0; i < 2; i++)
#pragma unroll
                for (int j = 0; j < 4; j++) {
                    MMA16816(acc[i][j], ah[i], bh[j]);
                    MMA16816(acc[i][j], ah[i], bl[j]);
                    MMA16816(acc[i][j], alf[i], bh[j]);
                }
        }
        __syncthreads();
    }

#pragma unroll
    for (int j = 0; j < 4; j++) {
        const int nn = n0 + wn + j * 8 + (lane & 3) * 2;
        const float blo = __ldg(&b1[nn]);
        const float bhi = __ldg(&b1[nn + 1]);
#pragma unroll
        for (int i = 0; i < 2; i++)
#pragma unroll
            for (int rr = 0; rr < 2; rr++) {
                const int m = m0 + wm + i * 16 + (lane >> 2) + rr * 8;
                float x0 = acc[i][j][rr * 2 + 0] + blo;
                float x1 = acc[i][j][rr * 2 + 1] + bhi;
                float g0 = x0 * normcdff(x0);
                float g1 = x1 * normcdff(x1);
                uint32_t ph = cvt2bf(__bfloat162float(__float2bfloat16(g1)) * 0.f + g1, g0);
                // exact split (packed): recompute properly
                uint32_t h01 = cvt2bf(g1, g0);
                float l0 = g0 - __uint_as_float(h01 << 16);
                float l1 = g1 - __uint_as_float(h01 & 0xFFFF0000u);
                uint32_t l01 = cvt2bf(l1, l0);
                (void)ph;
                *reinterpret_cast<uint32_t*>(&g_Hh[(size_t)m * 384 + nn]) = h01;
                *reinterpret_cast<uint32_t*>(&g_Hl[(size_t)m * 384 + nn]) = l01;
            }
    }
}

// ---------------- MLP2: 64x64 split GEMM (unchanged) ------------------------
#define MATS (64 * TSR)
#define STG  (4 * MATS)
#define NCH2 (384 / BK)

__global__ __launch_bounds__(128) void mlp2_mma(
    const float* __restrict__ b2, float* __restrict__ out)
{
    __shared__ __align__(16) __nv_bfloat16 sm[2 * STG];

    const int t    = threadIdx.x;
    const int w    = t >> 5;
    const int lane = t & 31;
    const int m0   = blockIdx.x * 64;
    const int n0   = blockIdx.y * 64;
    const int lvl  = m0 >> 12;
    const uint32_t sb = smem_u32(sm);

    float acc[2][4][4];
#pragma unroll
    for (int i = 0; i < 2; i++)
#pragma unroll
        for (int j = 0; j < 4; j++)
#pragma unroll
            for (int r = 0; r < 4; r++) acc[i][j][r] = 0.f;

    const __nv_bfloat16* gbase[4] = {
        g_Hh + (size_t)m0 * 384, g_Hl + (size_t)m0 * 384,
        g_W2h + (size_t)n0 * 384, g_W2l + (size_t)n0 * 384 };

    auto load_stage = [&](int ch, int st) {
#pragma unroll
        for (int it = 0; it < 8; it++) {
            const int u   = t + 128 * it;
            const int mat = u >> 8;
            const int row = (u >> 2) & 63;
            const int c16 = u & 3;
            const __nv_bfloat16* src =
                gbase[mat] + (size_t)row * 384 + ch * BK + c16 * 8;
            const uint32_t dst =
                sb + (uint32_t)(st * STG + mat * MATS + row * TSR + c16 * 8) * 2;
            CP16(dst, src);
        }
        CP_COMMIT();
    };

    load_stage(0, 0);

    const int wm = (w & 1) * 32;
    const int wn = (w >> 1) * 32;

    for (int ch = 0; ch < NCH2; ch++) {
        if (ch + 1 < NCH2) {
            load_stage(ch + 1, (ch + 1) & 1);
            asm volatile("cp.async.wait_group 1;" ::: "memory");
        } else {
            asm volatile("cp.async.wait_group 0;" ::: "memory");
        }
        __syncthreads();

        const uint32_t sa = sb + (uint32_t)((ch & 1) * STG) * 2;
        const uint32_t Ah = sa;
        const uint32_t Al = sa + MATS * 2;
        const uint32_t Bh = sa + 2 * MATS * 2;
        const uint32_t Bl = sa + 3 * MATS * 2;

#pragma unroll
        for (int ks = 0; ks < 2; ks++) {
            const int kc = ks * 16;
            uint32_t ah[2][4], alf[2][4], bh[4][2], bl[4][2];
#pragma unroll
            for (int i = 0; i < 2; i++) {
                const uint32_t off =
                    (uint32_t)((wm + i * 16 + (lane & 15)) * TSR + kc + (lane >> 4) * 8) * 2;
                LDSM4(ah[i], Ah + off);
                LDSM4(alf[i], Al + off);
            }
#pragma unroll
            for (int p = 0; p < 2; p++) {
                const uint32_t off =
                    (uint32_t)((wn + p * 16 + ((lane >> 4) & 1) * 8 + (lane & 7)) * TSR
                               + kc + ((lane >> 3) & 1) * 8) * 2;
                uint32_t rh[4], rl[4];
                LDSM4(rh, Bh + off);
                LDSM4(rl, Bl + off);
                bh[2 * p][0] = rh[0]; bh[2 * p][1] = rh[1];
                bh[2 * p + 1][0] = rh[2]; bh[2 * p + 1][1] = rh[3];
                bl[2 * p][0] = rl[0]; bl[2 * p][1] = rl[1];
                bl[2 * p + 1][0] = rl[2]; bl[2 * p + 1][1] = rl[3];
            }
#pragma unroll
            for (int i = 0; i < 2; i++)
#pragma unroll
                for (int j = 0; j < 4; j++) {
                    MMA16816(acc[i][j], ah[i], bh[j]);
                    MMA16816(acc[i][j], ah[i], bl[j]);
                    MMA16816(acc[i][j], alf[i], bh[j]);
                }
        }
        __syncthreads();
    }

#pragma unroll
    for (int j = 0; j < 4; j++) {
        const int nn = n0 + wn + j * 8 + (lane & 3) * 2;
        const float blo = __ldg(&b2[nn]);
        const float bhi = __ldg(&b2[nn + 1]);
#pragma unroll
        for (int i = 0; i < 2; i++)
#pragma unroll
            for (int rr = 0; rr < 2; rr++) {
                const int m  = m0 + wm + i * 16 + (lane >> 2) + rr * 8;
                const int pt = m & (NPTS - 1);
                float2 o = make_float2(acc[i][j][rr * 2 + 0] + blo,
                                       acc[i][j][rr * 2 + 1] + bhi);
                *reinterpret_cast<float2*>(&out[(size_t)pt * 1024 + lvl * 256 + nn]) = o;
            }
    }
}

// ---------------------------------------------------------------------------
extern "C" void kernel_launch(void* const* d_in, const int* in_sizes, int n_in,
                              void* d_out, int out_size)
{
    const float *fm[4], *tf[4], *coords, *w1, *b1, *w2, *b2;
    const int TFE = 49 * NPTS * CC;

    if (n_in >= 13 && in_sizes[1] == TFE) {
        for (int i = 0; i < 4; i++) {
            fm[i] = (const float*)d_in[2 * i];
            tf[i] = (const float*)d_in[2 * i + 1];
        }
        coords = (const float*)d_in[8];
    } else {
        for (int i = 0; i < 4; i++) {
            fm[i] = (const float*)d_in[i];
            tf[i] = (const float*)d_in[5 + i];
        }
        coords = (const float*)d_in[4];
    }
    w1 = (const float*)d_in[9];
    b1 = (const float*)d_in[10];
    w2 = (const float*)d_in[11];
    b2 = (const float*)d_in[12];
    float* out = (float*)d_out;

    CorrParams P;
    const int Hs[4] = {96, 48, 24, 12};
    const int Wd[4] = {128, 64, 32, 16};
    for (int i = 0; i < 4; i++) {
        P.fmap[i]  = fm[i];
        P.tfeat[i] = tf[i];
        P.Hh[i]    = Hs[i];
        P.Ww[i]    = Wd[i];
        P.ls[i]    = 1.0f / (float)(1 << i);
    }

    const int M1_SMEM = 2 * M1STG * 2;   // 61440 B
    cudaFuncSetAttribute(mlp1_mma, cudaFuncAttributeMaxDynamicSharedMemorySize,
                         M1_SMEM);

    split_w1<<<2401, 128>>>(w1);
    split_w2<<<384, 128>>>(w2);
    corr_main<<<dim3(NPTS, 4), 128>>>(P, coords);
    mlp1_mma<<<dim3(256, 3), 256, M1_SMEM>>>(b1);
    mlp2_mma<<<dim3(256, 4), 128>>>(b2, out);
}

// round 10
// speedup vs baseline: 1.1258x; 1.1258x over previous
#include <cuda_runtime.h>
#include <cuda_bf16.h>
#include <math.h>
#include <stdint.h>

// ---------------------------------------------------------------------------
// Round 10:
//   corr : GEMM on RAW patch (m = yy*8+xx), bilinear applied post-GEMM on the
//          64x49 fp32 D in smem (vectorized). X K-layout = hw*52+q (aligned),
//          w1 prep permuted to match. smem ~33KB.
//   mlp1 : 64x64/128thr, 3-stage cp.async ring, one sync per chunk, K=2560.
//   mlp2 : unchanged 2-stage 64x64 split GEMM.
// ---------------------------------------------------------------------------

#define NPTS 4096
#define CC   128
#define LDK  2560              // 49 rows * 52 padded cols = 2548, rounded to 32
#define MTOT (4 * NPTS)

__device__ __nv_bfloat16 g_Xh[(size_t)MTOT * LDK];
__device__ __nv_bfloat16 g_Xl[(size_t)MTOT * LDK];
__device__ __nv_bfloat16 g_Wh[384 * LDK];
__device__ __nv_bfloat16 g_Wl[384 * LDK];
__device__ __nv_bfloat16 g_Hh[MTOT * 384];
__device__ __nv_bfloat16 g_Hl[MTOT * 384];
__device__ __nv_bfloat16 g_W2h[256 * 384];
__device__ __nv_bfloat16 g_W2l[256 * 384];

// ---------------- helpers ----------------------------------------------------
__device__ __forceinline__ uint32_t smem_u32(const void* p) {
    uint32_t a;
    asm("{ .reg .u64 t; cvta.to.shared.u64 t, %1; cvt.u32.u64 %0, t; }"
        : "=r"(a) : "l"(p));
    return a;
}

#define LDSM4(r, addr)                                                        \
    asm volatile("ldmatrix.sync.aligned.m8n8.x4.shared.b16 {%0,%1,%2,%3}, [%4];" \
        : "=r"((r)[0]), "=r"((r)[1]), "=r"((r)[2]), "=r"((r)[3]) : "r"(addr))

#define LDSM4T(r, addr)                                                       \
    asm volatile("ldmatrix.sync.aligned.m8n8.x4.trans.shared.b16 {%0,%1,%2,%3}, [%4];" \
        : "=r"((r)[0]), "=r"((r)[1]), "=r"((r)[2]), "=r"((r)[3]) : "r"(addr))

#define MMA16816(d, a, b)                                                     \
    asm volatile("mma.sync.aligned.m16n8k16.row.col.f32.bf16.bf16.f32 "       \
        "{%0,%1,%2,%3}, {%4,%5,%6,%7}, {%8,%9}, {%0,%1,%2,%3};"               \
        : "+f"((d)[0]), "+f"((d)[1]), "+f"((d)[2]), "+f"((d)[3])              \
        : "r"((a)[0]), "r"((a)[1]), "r"((a)[2]), "r"((a)[3]),                 \
          "r"((b)[0]), "r"((b)[1]))

#define CP16(dst, src)                                                        \
    asm volatile("cp.async.cg.shared.global [%0], [%1], 16;" :: "r"(dst), "l"(src))
#define CP_COMMIT() asm volatile("cp.async.commit_group;" ::: "memory")

__device__ __forceinline__ void split_bf16(float x, __nv_bfloat16& h, __nv_bfloat16& l) {
    h = __float2bfloat16(x);
    l = __float2bfloat16(x - __bfloat162float(h));
}

__device__ __forceinline__ uint32_t cvt2bf(float hi, float lo) {
    uint32_t d;
    asm("cvt.rn.bf16x2.f32 %0, %1, %2;" : "=r"(d) : "f"(hi), "f"(lo));
    return d;
}

__device__ __forceinline__ void split4(float o0, float o1, float o2, float o3,
                                       uint2& hh, uint2& ll) {
    uint32_t h01 = cvt2bf(o1, o0);
    uint32_t h23 = cvt2bf(o3, o2);
    float l0 = o0 - __uint_as_float(h01 << 16);
    float l1 = o1 - __uint_as_float(h01 & 0xFFFF0000u);
    float l2 = o2 - __uint_as_float(h23 << 16);
    float l3 = o3 - __uint_as_float(h23 & 0xFFFF0000u);
    hh = make_uint2(h01, h23);
    ll = make_uint2(cvt2bf(l1, l0), cvt2bf(l3, l2));
}

// ---------------- corr kernel ------------------------------------------------
#define TSR  40     // T tile row stride (bf16)
#define ASTR 72     // A (k-major [c][m]) row stride (bf16)
#define DS   52     // D smem row stride (f32)

struct CorrParams {
    const float* fmap[4];
    const float* tfeat[4];
    int   Hh[4];
    int   Ww[4];
    float ls[4];
};

// q[I] = rv[K+I] if in window else 0 (compile-time)
template<int K, int I>
struct SEL {
    static __device__ __forceinline__ void run(float* q, const float* rv) {
        if constexpr (K + I >= 0 && K + I <= 11) q[I] = rv[K + I];
        else q[I] = 0.f;
        if constexpr (I < 7) SEL<K, I + 1>::run(q, rv);
    }
};
template<int K>
__device__ __forceinline__ void sel8(float* q, const float* rv) {
    SEL<K, 0>::run(q, rv);
}

__global__ __launch_bounds__(128) void corr_main(
    CorrParams P, const float* __restrict__ coords)
{
    // UD: tfeat fp32 double-stage (2x1568 f32) then aliased as D[64][52] f32
    __shared__ __align__(16) float UD[3328];
    __shared__ __align__(16) __nv_bfloat16 tAh[32 * ASTR];
    __shared__ __align__(16) __nv_bfloat16 tAl[32 * ASTR];
    __shared__ __align__(16) __nv_bfloat16 tTh[64 * TSR];
    __shared__ __align__(16) __nv_bfloat16 tTl[64 * TSR];

    const int n    = blockIdx.x;
    const int lvl  = blockIdx.y;
    const int t    = threadIdx.x;
    const int w    = t >> 5;
    const int lane = t & 31;

    const float* __restrict__ fmap  = P.fmap[lvl];
    const float* __restrict__ tfeat = P.tfeat[lvl];
    const int Hh = P.Hh[lvl], Ww = P.Ww[lvl];

    const float xl = __ldg(&coords[2 * n + 0]) * P.ls[lvl];
    const float yl = __ldg(&coords[2 * n + 1]) * P.ls[lvl];
    const float xf = floorf(xl), yf = floorf(yl);
    const float wx = xl - xf, wy = yl - yf;
    const int bx = (int)xf - 3, by = (int)yf - 3;
    const float w00 = (1.f - wy) * (1.f - wx);
    const float w01 = (1.f - wy) * wx;
    const float w10 = wy * (1.f - wx);
    const float w11 = wy * wx;

    int s  = min(max(bx, 0), Ww - 8);
    int al = min(max(s & ~3, 0), Ww - 12);
    const int shift = bx - al;

    const uint32_t aAh = smem_u32(tAh);
    const uint32_t aAl = smem_u32(tAl);
    const uint32_t aTh = smem_u32(tTh);
    const uint32_t aTl = smem_u32(tTl);
    const uint32_t aTf = smem_u32(UD);

    const int wm = (w & 1) * 32;
    const int wn = (w >> 1) * 32;

    float acc[2][4][4];
#pragma unroll
    for (int i = 0; i < 2; i++)
#pragma unroll
        for (int j = 0; j < 4; j++)
#pragma unroll
            for (int r = 0; r < 4; r++) acc[i][j][r] = 0.f;

    auto issue_tfeat = [&](int qi, int buf) {
#pragma unroll
        for (int e = t; e < 392; e += 128) {
            const int q  = e >> 3;
            const int c4 = (e & 7) << 2;
            CP16(aTf + (uint32_t)(buf * 1568 + e * 4) * 4,
                 tfeat + (size_t)q * (NPTS * CC) + n * CC + qi * 32 + c4);
        }
        CP_COMMIT();
    };
    issue_tfeat(0, 0);

    for (int qi = 0; qi < 4; qi++) {
        const int c0 = qi * 32;

        // ---- raw patch -> A tiles [c][m], m = yy*8+xx (split at load) ----
#pragma unroll
        for (int it = 0; it < 2; it++) {
            const int r  = t + 128 * it;
            const int c  = r >> 3;
            const int yy = r & 7;
            const int gy = by + yy;
            float rv[12];
#pragma unroll
            for (int j = 0; j < 12; j++) rv[j] = 0.f;
            if (gy >= 0 && gy < Hh) {
                const float4* rp = reinterpret_cast<const float4*>(
                    fmap + ((size_t)(c0 + c) * Hh + gy) * Ww + al);
                float4 f0 = __ldg(rp), f1 = __ldg(rp + 1), f2 = __ldg(rp + 2);
                rv[0]=f0.x; rv[1]=f0.y; rv[2]=f0.z; rv[3]=f0.w;
                rv[4]=f1.x; rv[5]=f1.y; rv[6]=f1.z; rv[7]=f1.w;
                rv[8]=f2.x; rv[9]=f2.y; rv[10]=f2.z; rv[11]=f2.w;
            }
            float q[8];
            switch (shift) {
                case -3: sel8<-3>(q, rv); break;
                case -2: sel8<-2>(q, rv); break;
                case -1: sel8<-1>(q, rv); break;
                case  0: sel8< 0>(q, rv); break;
                case  1: sel8< 1>(q, rv); break;
                case  2: sel8< 2>(q, rv); break;
                case  3: sel8< 3>(q, rv); break;
                case  4: sel8< 4>(q, rv); break;
                case  5: sel8< 5>(q, rv); break;
                case  6: sel8< 6>(q, rv); break;
                case  7: sel8< 7>(q, rv); break;
                default: sel8< 8>(q, rv); break;
            }
            uint2 h0, l0, h1, l1;
            split4(q[0], q[1], q[2], q[3], h0, l0);
            split4(q[4], q[5], q[6], q[7], h1, l1);
            const int pos = c * ASTR + yy * 8;
            *reinterpret_cast<uint4*>(&tAh[pos]) = make_uint4(h0.x, h0.y, h1.x, h1.y);
            *reinterpret_cast<uint4*>(&tAl[pos]) = make_uint4(l0.x, l0.y, l1.x, l1.y);
        }

        if (qi + 1 < 4) {
            issue_tfeat(qi + 1, (qi + 1) & 1);
            asm volatile("cp.async.wait_group 1;" ::: "memory");
        } else {
            asm volatile("cp.async.wait_group 0;" ::: "memory");
        }
        __syncthreads();

        // ---- tfeat quarter -> T tiles ----
        const float* Tc = UD + (qi & 1) * 1568;
#pragma unroll
        for (int e = t; e < 392; e += 128) {
            const int q  = e >> 3;
            const int c4 = (e & 7) << 2;
            float4 v = *reinterpret_cast<const float4*>(&Tc[e * 4]);
            uint2 hh, ll;
            split4(v.x, v.y, v.z, v.w, hh, ll);
            *reinterpret_cast<uint2*>(&tTh[q * TSR + c4]) = hh;
            *reinterpret_cast<uint2*>(&tTl[q * TSR + c4]) = ll;
        }
        __syncthreads();

        // ---- MMA: A via ldmatrix.trans (k-major), B via ldmatrix ----
#pragma unroll
        for (int ks = 0; ks < 2; ks++) {
            const int kc = ks * 16;
            uint32_t ah[2][4], alf[2][4], bh[4][2], bl[4][2];
            const int arow = kc + (lane & 7) + ((lane >> 4) << 3);
#pragma unroll
            for (int i = 0; i < 2; i++) {
                const int acol = wm + i * 16 + ((lane >> 3) & 1) * 8;
                const uint32_t off = (uint32_t)(arow * ASTR + acol) * 2;
                LDSM4T(ah[i], aAh + off);
                LDSM4T(alf[i], aAl + off);
            }
#pragma unroll
            for (int p = 0; p < 2; p++) {
                const uint32_t off =
                    (uint32_t)((wn + p * 16 + ((lane >> 4) & 1) * 8 + (lane & 7)) * TSR
                               + kc + ((lane >> 3) & 1) * 8) * 2;
                uint32_t rh[4], rl[4];
                LDSM4(rh, aTh + off);
                LDSM4(rl, aTl + off);
                bh[2 * p][0] = rh[0]; bh[2 * p][1] = rh[1];
                bh[2 * p + 1][0] = rh[2]; bh[2 * p + 1][1] = rh[3];
                bl[2 * p][0] = rl[0]; bl[2 * p][1] = rl[1];
                bl[2 * p + 1][0] = rl[2]; bl[2 * p + 1][1] = rl[3];
            }
#pragma unroll
            for (int i = 0; i < 2; i++)
#pragma unroll
                for (int j = 0; j < 4; j++) {
                    MMA16816(acc[i][j], ah[i], bh[j]);
                    MMA16816(acc[i][j], ah[i], bl[j]);
                    MMA16816(acc[i][j], alf[i], bh[j]);
                }
        }
        __syncthreads();
    }

    // ---- D store: acc -> UD as D[m][q] f32 (Tf dead now) ----
    float* D = UD;
#pragma unroll
    for (int i = 0; i < 2; i++)
#pragma unroll
        for (int rr = 0; rr < 2; rr++) {
            const int m = wm + i * 16 + (lane >> 2) + rr * 8;
#pragma unroll
            for (int j = 0; j < 4; j++) {
                const int q0 = wn + j * 8 + (lane & 3) * 2;
                if (q0 < 48) {
                    *reinterpret_cast<float2*>(&D[m * DS + q0]) =
                        make_float2(acc[i][j][rr * 2], acc[i][j][rr * 2 + 1]);
                } else if (q0 == 48) {
                    D[m * DS + 48] = acc[i][j][rr * 2];
                }
            }
        }
    __syncthreads();

    // ---- bilinear blend on D -> X (hw*52+q layout) ----
    __nv_bfloat16* Xh = g_Xh + ((size_t)lvl * NPTS + n) * LDK;
    __nv_bfloat16* Xl = g_Xl + ((size_t)lvl * NPTS + n) * LDK;
    for (int e = t; e < 637; e += 128) {          // 49 hw * 13 quads
        const int hw = e / 13;
        const int qq = e - hw * 13;
        const int q0 = qq * 4;
        const int oi = hw / 7;
        const int oj = hw - oi * 7;
        const int m00 = oj * 8 + oi;
        float4 a = *reinterpret_cast<const float4*>(&D[(m00)     * DS + q0]);
        float4 b = *reinterpret_cast<const float4*>(&D[(m00 + 1) * DS + q0]);
        float4 c = *reinterpret_cast<const float4*>(&D[(m00 + 8) * DS + q0]);
        float4 d = *reinterpret_cast<const float4*>(&D[(m00 + 9) * DS + q0]);
        float4 o;
        o.x = w00 * a.x + w01 * b.x + w10 * c.x + w11 * d.x;
        o.y = w00 * a.y + w01 * b.y + w10 * c.y + w11 * d.y;
        o.z = w00 * a.z + w01 * b.z + w10 * c.z + w11 * d.z;
        o.w = w00 * a.w + w01 * b.w + w10 * c.w + w11 * d.w;
        uint2 hh, ll;
        split4(o.x, o.y, o.z, o.w, hh, ll);
        const int xi = hw * 52 + q0;
        if (q0 < 48) {
            *reinterpret_cast<uint2*>(&Xh[xi]) = hh;
            *reinterpret_cast<uint2*>(&Xl[xi]) = ll;
        } else {   // q0 == 48: single valid element
            __nv_bfloat16 h, l;
            split_bf16(o.x, h, l);
            Xh[xi] = h; Xl[xi] = l;
        }
    }
}

// ---------------- prep: split + transpose + permute weights -----------------
__global__ __launch_bounds__(128) void split_w1(const float* __restrict__ w1)
{
    const int k  = blockIdx.x;             // 0..2400 (reference k = hw*49+q)
    const int hw = k / 49;
    const int q  = k - hw * 49;
    const int kp = hw * 52 + q;            // permuted k to match X layout
    const float* row = w1 + (size_t)k * 384;
    for (int n = threadIdx.x; n < 384; n += 128) {
        __nv_bfloat16 h, l;
        split_bf16(row[n], h, l);
        g_Wh[(size_t)n * LDK + kp] = h;
        g_Wl[(size_t)n * LDK + kp] = l;
    }
}

__global__ __launch_bounds__(128) void split_w2(const float* __restrict__ w2)
{
    const int k = blockIdx.x;
    const float* row = w2 + (size_t)k * 256;
    for (int n = threadIdx.x; n < 256; n += 128) {
        __nv_bfloat16 h, l;
        split_bf16(row[n], h, l);
        g_W2h[(size_t)n * 384 + k] = h;
        g_W2l[(size_t)n * 384 + k] = l;
    }
}

// ---------------- MLP1: 64x64, 3-stage ring, one sync per chunk -------------
#define BK    32
#define MATS  (64 * TSR)          // 2560 bf16 per matrix tile
#define M1STG (4 * MATS)          // per-stage (Ah,Al,Bh,Bl)
#define NCH   (LDK / BK)          // 80

__global__ __launch_bounds__(128) void mlp1_mma(const float* __restrict__ b1)
{
    extern __shared__ __align__(16) __nv_bfloat16 sm1[];   // 3 * M1STG

    const int t    = threadIdx.x;
    const int w    = t >> 5;
    const int lane = t & 31;
    const int m0   = blockIdx.x * 64;
    const int n0   = blockIdx.y * 64;
    const uint32_t sb = smem_u32(sm1);

    float acc[2][4][4];
#pragma unroll
    for (int i = 0; i < 2; i++)
#pragma unroll
        for (int j = 0; j < 4; j++)
#pragma unroll
            for (int r = 0; r < 4; r++) acc[i][j][r] = 0.f;

    const __nv_bfloat16* gbase[4] = {
        g_Xh + (size_t)m0 * LDK, g_Xl + (size_t)m0 * LDK,
        g_Wh + (size_t)n0 * LDK, g_Wl + (size_t)n0 * LDK };

    auto load_stage = [&](int ch, int st) {
#pragma unroll
        for (int it = 0; it < 8; it++) {
            const int u   = t + 128 * it;
            const int mat = u >> 8;
            const int row = (u >> 2) & 63;
            const int c16 = u & 3;
            const __nv_bfloat16* src =
                gbase[mat] + (size_t)row * LDK + ch * BK + c16 * 8;
            const uint32_t dst =
                sb + (uint32_t)(st * M1STG + mat * MATS + row * TSR + c16 * 8) * 2;
            CP16(dst, src);
        }
        CP_COMMIT();
    };

    load_stage(0, 0);
    load_stage(1, 1);

    const int wm = (w & 1) * 32;
    const int wn = (w >> 1) * 32;

    for (int ch = 0; ch < NCH; ch++) {
        if (ch + 1 < NCH) {
            asm volatile("cp.async.wait_group 1;" ::: "memory");
        } else {
            asm volatile("cp.async.wait_group 0;" ::: "memory");
        }
        __syncthreads();
        if (ch + 2 < NCH) load_stage(ch + 2, (ch + 2) % 3);

        const uint32_t sa = sb + (uint32_t)((ch % 3) * M1STG) * 2;
        const uint32_t Ah = sa;
        const uint32_t Al = sa + MATS * 2;
        const uint32_t Bh = sa + 2 * MATS * 2;
        const uint32_t Bl = sa + 3 * MATS * 2;

#pragma unroll
        for (int ks = 0; ks < 2; ks++) {
            const int kc = ks * 16;
            uint32_t ah[2][4], alf[2][4], bh[4][2], bl[4][2];
#pragma unroll
            for (int i = 0; i < 2; i++) {
                const uint32_t off =
                    (uint32_t)((wm + i * 16 + (lane & 15)) * TSR + kc + (lane >> 4) * 8) * 2;
                LDSM4(ah[i], Ah + off);
                LDSM4(alf[i], Al + off);
            }
#pragma unroll
            for (int p = 0; p < 2; p++) {
                const uint32_t off =
                    (uint32_t)((wn + p * 16 + ((lane >> 4) & 1) * 8 + (lane & 7)) * TSR
                               + kc + ((lane >> 3) & 1) * 8) * 2;
                uint32_t rh[4], rl[4];
                LDSM4(rh, Bh + off);
                LDSM4(rl, Bl + off);
                bh[2 * p][0] = rh[0]; bh[2 * p][1] = rh[1];
                bh[2 * p + 1][0] = rh[2]; bh[2 * p + 1][1] = rh[3];
                bl[2 * p][0] = rl[0]; bl[2 * p][1] = rl[1];
                bl[2 * p + 1][0] = rl[2]; bl[2 * p + 1][1] = rl[3];
            }
#pragma unroll
            for (int i = 0; i < 2; i++)
#pragma unroll
                for (int j = 0; j < 4; j++) {
                    MMA16816(acc[i][j], ah[i], bh[j]);
                    MMA16816(acc[i][j], ah[i], bl[j]);
                    MMA16816(acc[i][j], alf[i], bh[j]);
                }
        }
    }

    // ---- epilogue: +bias, GELU, split -> g_Hh / g_Hl ----
#pragma unroll
    for (int j = 0; j < 4; j++) {
        const int nn = n0 + wn + j * 8 + (lane & 3) * 2;
        const float blo = __ldg(&b1[nn]);
        const float bhi = __ldg(&b1[nn + 1]);
#pragma unroll
        for (int i = 0; i < 2; i++)
#pragma unroll
            for (int rr = 0; rr < 2; rr++) {
                const int m = m0 + wm + i * 16 + (lane >> 2) + rr * 8;
                float x0 = acc[i][j][rr * 2 + 0] + blo;
                float x1 = acc[i][j][rr * 2 + 1] + bhi;
                float g0 = x0 * normcdff(x0);
                float g1 = x1 * normcdff(x1);
                uint32_t h01 = cvt2bf(g1, g0);
                float l0 = g0 - __uint_as_float(h01 << 16);
                float l1 = g1 - __uint_as_float(h01 & 0xFFFF0000u);
                uint32_t l01 = cvt2bf(l1, l0);
                *reinterpret_cast<uint32_t*>(&g_Hh[(size_t)m * 384 + nn]) = h01;
                *reinterpret_cast<uint32_t*>(&g_Hl[(size_t)m * 384 + nn]) = l01;
            }
    }
}

// ---------------- MLP2: 64x64 split GEMM (2-stage, unchanged) ---------------
#define MT2  (64 * TSR)
#define ST2  (4 * MT2)
#define NCH2 (384 / BK)

__global__ __launch_bounds__(128) void mlp2_mma(
    const float* __restrict__ b2, float* __restrict__ out)
{
    __shared__ __align__(16) __nv_bfloat16 sm[2 * ST2];

    const int t    = threadIdx.x;
    const int w    = t >> 5;
    const int lane = t & 31;
    const int m0   = blockIdx.x * 64;
    const int n0   = blockIdx.y * 64;
    const int lvl  = m0 >> 12;
    const uint32_t sb = smem_u32(sm);

    float acc[2][4][4];
#pragma unroll
    for (int i = 0; i < 2; i++)
#pragma unroll
        for (int j = 0; j < 4; j++)
#pragma unroll
            for (int r = 0; r < 4; r++) acc[i][j][r] = 0.f;

    const __nv_bfloat16* gbase[4] = {
        g_Hh + (size_t)m0 * 384, g_Hl + (size_t)m0 * 384,
        g_W2h + (size_t)n0 * 384, g_W2l + (size_t)n0 * 384 };

    auto load_stage = [&](int ch, int st) {
#pragma unroll
        for (int it = 0; it < 8; it++) {
            const int u   = t + 128 * it;
            const int mat = u >> 8;
            const int row = (u >> 2) & 63;
            const int c16 = u & 3;
            const __nv_bfloat16* src =
                gbase[mat] + (size_t)row * 384 + ch * BK + c16 * 8;
            const uint32_t dst =
                sb + (uint32_t)(st * ST2 + mat * MT2 + row * TSR + c16 * 8) * 2;
            CP16(dst, src);
        }
        CP_COMMIT();
    };

    load_stage(0, 0);

    const int wm = (w & 1) * 32;
    const int wn = (w >> 1) * 32;

    for (int ch = 0; ch < NCH2; ch++) {
        if (ch + 1 < NCH2) {
            load_stage(ch + 1, (ch + 1) & 1);
            asm volatile("cp.async.wait_group 1;" ::: "memory");
        } else {
            asm volatile("cp.async.wait_group 0;" ::: "memory");
        }
        __syncthreads();

        const uint32_t sa = sb + (uint32_t)((ch & 1) * ST2) * 2;
        const uint32_t Ah = sa;
        const uint32_t Al = sa + MT2 * 2;
        const uint32_t Bh = sa + 2 * MT2 * 2;
        const uint32_t Bl = sa + 3 * MT2 * 2;

#pragma unroll
        for (int ks = 0; ks < 2; ks++) {
            const int kc = ks * 16;
            uint32_t ah[2][4], alf[2][4], bh[4][2], bl[4][2];
#pragma unroll
            for (int i = 0; i < 2; i++) {
                const uint32_t off =
                    (uint32_t)((wm + i * 16 + (lane & 15)) * TSR + kc + (lane >> 4) * 8) * 2;
                LDSM4(ah[i], Ah + off);
                LDSM4(alf[i], Al + off);
            }
#pragma unroll
            for (int p = 0; p < 2; p++) {
                const uint32_t off =
                    (uint32_t)((wn + p * 16 + ((lane >> 4) & 1) * 8 + (lane & 7)) * TSR
                               + kc + ((lane >> 3) & 1) * 8) * 2;
                uint32_t rh[4], rl[4];
                LDSM4(rh, Bh + off);
                LDSM4(rl, Bl + off);
                bh[2 * p][0] = rh[0]; bh[2 * p][1] = rh[1];
                bh[2 * p + 1][0] = rh[2]; bh[2 * p + 1][1] = rh[3];
                bl[2 * p][0] = rl[0]; bl[2 * p][1] = rl[1];
                bl[2 * p + 1][0] = rl[2]; bl[2 * p + 1][1] = rl[3];
            }
#pragma unroll
            for (int i = 0; i < 2; i++)
#pragma unroll
                for (int j = 0; j < 4; j++) {
                    MMA16816(acc[i][j], ah[i], bh[j]);
                    MMA16816(acc[i][j], ah[i], bl[j]);
                    MMA16816(acc[i][j], alf[i], bh[j]);
                }
        }
        __syncthreads();
    }

#pragma unroll
    for (int j = 0; j < 4; j++) {
        const int nn = n0 + wn + j * 8 + (lane & 3) * 2;
        const float blo = __ldg(&b2[nn]);
        const float bhi = __ldg(&b2[nn + 1]);
#pragma unroll
        for (int i = 0; i < 2; i++)
#pragma unroll
            for (int rr = 0; rr < 2; rr++) {
                const int m  = m0 + wm + i * 16 + (lane >> 2) + rr * 8;
                const int pt = m & (NPTS - 1);
                float2 o = make_float2(acc[i][j][rr * 2 + 0] + blo,
                                       acc[i][j][rr * 2 + 1] + bhi);
                *reinterpret_cast<float2*>(&out[(size_t)pt * 1024 + lvl * 256 + nn]) = o;
            }
    }
}

// ---------------------------------------------------------------------------
extern "C" void kernel_launch(void* const* d_in, const int* in_sizes, int n_in,
                              void* d_out, int out_size)
{
    const float *fm[4], *tf[4], *coords, *w1, *b1, *w2, *b2;
    const int TFE = 49 * NPTS * CC;

    if (n_in >= 13 && in_sizes[1] == TFE) {
        for (int i = 0; i < 4; i++) {
            fm[i] = (const float*)d_in[2 * i];
            tf[i] = (const float*)d_in[2 * i + 1];
        }
        coords = (const float*)d_in[8];
    } else {
        for (int i = 0; i < 4; i++) {
            fm[i] = (const float*)d_in[i];
            tf[i] = (const float*)d_in[5 + i];
        }
        coords = (const float*)d_in[4];
    }
    w1 = (const float*)d_in[9];
    b1 = (const float*)d_in[10];
    w2 = (const float*)d_in[11];
    b2 = (const float*)d_in[12];
    float* out = (float*)d_out;

    CorrParams P;
    const int Hs[4] = {96, 48, 24, 12};
    const int Wd[4] = {128, 64, 32, 16};
    for (int i = 0; i < 4; i++) {
        P.fmap[i]  = fm[i];
        P.tfeat[i] = tf[i];
        P.Hh[i]    = Hs[i];
        P.Ww[i]    = Wd[i];
        P.ls[i]    = 1.0f / (float)(1 << i);
    }

    const int M1_SMEM = 3 * M1STG * 2;   // 61440 B
    cudaFuncSetAttribute(mlp1_mma, cudaFuncAttributeMaxDynamicSharedMemorySize,
                         M1_SMEM);

    split_w1<<<2401, 128>>>(w1);
    split_w2<<<384, 128>>>(w2);
    corr_main<<<dim3(NPTS, 4), 128>>>(P, coords);
    mlp1_mma<<<dim3(256, 6), 128, M1_SMEM>>>(b1);
    mlp2_mma<<<dim3(256, 4), 128>>>(b2, out);
}